// round 5
// baseline (speedup 1.0000x reference)
#include <cuda_runtime.h>

// out[i, j] = (2*x[i, j] + 3) / (i + 1), x is 8192x8192 fp32.
// HBM-bound streaming at ~90% of 8TB/s spec (537MB / 74.6us ncu).
// R5: THREADS=512 (halves CTA count -> less per-CTA front-end overhead),
// UNROLL=4 front-batched LDG.128, flat launch, streaming cache hints.

static constexpr int N_ROWS = 8192;
static constexpr int N_COLS = 8192;
static constexpr long long N_ELEMS = (long long)N_ROWS * N_COLS;   // 2^26
static constexpr long long N_VEC = N_ELEMS / 4;                    // 2^24 float4s
static constexpr int THREADS = 512;
static constexpr int UNROLL = 4;
// 2^24 / (512*4) = 8192 blocks, exact — no tail.
static constexpr int BLOCKS = (int)(N_VEC / (THREADS * UNROLL));

__global__ void __launch_bounds__(THREADS)
affine_rowdiv_kernel(const float4* __restrict__ in, float4* __restrict__ out) {
    long long base = (long long)blockIdx.x * (THREADS * UNROLL) + threadIdx.x;

    // Front-batch 4 independent LDG.128 per thread.
    float4 v[UNROLL];
#pragma unroll
    for (int k = 0; k < UNROLL; k++) {
        v[k] = __ldcs(&in[base + (long long)k * THREADS]);
    }

#pragma unroll
    for (int k = 0; k < UNROLL; k++) {
        long long idx = base + (long long)k * THREADS;
        // 2048 float4s per row -> row = idx >> 11
        int row = (int)(idx >> 11);
        float inv = 1.0f / (float)(row + 1);
        float4 r;
        r.x = fmaf(2.0f, v[k].x, 3.0f) * inv;
        r.y = fmaf(2.0f, v[k].y, 3.0f) * inv;
        r.z = fmaf(2.0f, v[k].z, 3.0f) * inv;
        r.w = fmaf(2.0f, v[k].w, 3.0f) * inv;
        __stcs(&out[idx], r);
    }
}

extern "C" void kernel_launch(void* const* d_in, const int* in_sizes, int n_in,
                              void* d_out, int out_size) {
    const float4* in = (const float4*)d_in[0];
    float4* out = (float4*)d_out;
    affine_rowdiv_kernel<<<BLOCKS, THREADS>>>(in, out);
}

// round 6
// speedup vs baseline: 1.0086x; 1.0086x over previous
#include <cuda_runtime.h>

// out[i, j] = (2*x[i, j] + 3) / (i + 1), x is 8192x8192 fp32.
// HBM-bound streaming at ~90% of 8TB/s effective (537MB / ~74.4us).
// R6: R4 shape (256T, UNROLL=4, flat 16384 CTAs — measured optimum across
// occ/MLP/block/persistent sweeps) + full 32-bit indexing (N_VEC = 2^24
// fits int) to trim IMAD.WIDE pairs from the issue stream.

static constexpr int N_ROWS = 8192;
static constexpr int N_COLS = 8192;
static constexpr int N_VEC = (N_ROWS / 4) * N_COLS;     // 2^24 float4s (fits int)
static constexpr int THREADS = 256;
static constexpr int UNROLL = 4;
// 2^24 / (256*4) = 16384 blocks, exact — no tail.
static constexpr int BLOCKS = N_VEC / (THREADS * UNROLL);

__global__ void __launch_bounds__(THREADS)
affine_rowdiv_kernel(const float4* __restrict__ in, float4* __restrict__ out) {
    int base = blockIdx.x * (THREADS * UNROLL) + threadIdx.x;

    // Front-batch 4 independent LDG.128 per thread.
    float4 v[UNROLL];
#pragma unroll
    for (int k = 0; k < UNROLL; k++) {
        v[k] = __ldcs(&in[base + k * THREADS]);
    }

#pragma unroll
    for (int k = 0; k < UNROLL; k++) {
        int idx = base + k * THREADS;
        // 2048 float4s per row -> row = idx >> 11
        int row = idx >> 11;
        float inv = 1.0f / (float)(row + 1);
        float4 r;
        r.x = fmaf(2.0f, v[k].x, 3.0f) * inv;
        r.y = fmaf(2.0f, v[k].y, 3.0f) * inv;
        r.z = fmaf(2.0f, v[k].z, 3.0f) * inv;
        r.w = fmaf(2.0f, v[k].w, 3.0f) * inv;
        __stcs(&out[idx], r);
    }
}

extern "C" void kernel_launch(void* const* d_in, const int* in_sizes, int n_in,
                              void* d_out, int out_size) {
    const float4* in = (const float4*)d_in[0];
    float4* out = (float4*)d_out;
    affine_rowdiv_kernel<<<BLOCKS, THREADS>>>(in, out);
}

// round 7
// speedup vs baseline: 1.0090x; 1.0004x over previous
#include <cuda_runtime.h>

// out[i, j] = (2*x[i, j] + 3) / (i + 1), x is 8192x8192 fp32.
// HBM-bound streaming at ~7.2 TB/s effective (90% of spec) — at the roofline.
// R7: final sweep point. THREADS=128, UNROLL=4 (grid 32768): halves per-CTA
// L1tex load batch vs 256T (R5 showed 512T hurt via L1tex queue contention;
// probing the opposite direction). Flat launch, front-batched LDG.128,
// streaming cache hints, 32-bit indexing.

static constexpr int N_ROWS = 8192;
static constexpr int N_COLS = 8192;
static constexpr int N_VEC = (N_ROWS / 4) * N_COLS;     // 2^24 float4s (fits int)
static constexpr int THREADS = 128;
static constexpr int UNROLL = 4;
// 2^24 / (128*4) = 32768 blocks, exact — no tail.
static constexpr int BLOCKS = N_VEC / (THREADS * UNROLL);

__global__ void __launch_bounds__(THREADS)
affine_rowdiv_kernel(const float4* __restrict__ in, float4* __restrict__ out) {
    int base = blockIdx.x * (THREADS * UNROLL) + threadIdx.x;

    // Front-batch 4 independent LDG.128 per thread.
    float4 v[UNROLL];
#pragma unroll
    for (int k = 0; k < UNROLL; k++) {
        v[k] = __ldcs(&in[base + k * THREADS]);
    }

#pragma unroll
    for (int k = 0; k < UNROLL; k++) {
        int idx = base + k * THREADS;
        // 2048 float4s per row -> row = idx >> 11
        int row = idx >> 11;
        float inv = 1.0f / (float)(row + 1);
        float4 r;
        r.x = fmaf(2.0f, v[k].x, 3.0f) * inv;
        r.y = fmaf(2.0f, v[k].y, 3.0f) * inv;
        r.z = fmaf(2.0f, v[k].z, 3.0f) * inv;
        r.w = fmaf(2.0f, v[k].w, 3.0f) * inv;
        __stcs(&out[idx], r);
    }
}

extern "C" void kernel_launch(void* const* d_in, const int* in_sizes, int n_in,
                              void* d_out, int out_size) {
    const float4* in = (const float4*)d_in[0];
    float4* out = (float4*)d_out;
    affine_rowdiv_kernel<<<BLOCKS, THREADS>>>(in, out);
}